// round 17
// baseline (speedup 1.0000x reference)
#include <cuda_runtime.h>
#include <cuda_fp16.h>
#include <stdint.h>

#define FDIM   1024
#define BATCH  256
#define NCLS   1000
#define CPAD   1024
#define KROW   65536
#define CB     32          // class blocks of 32
#define FS     9           // f slices (uneven epochs: 4x29 + 5x28)
#define THREADS 256
#define TSTRIDE 33         // tile row stride in words
#define FTILE  (64 * TSTRIDE)          // words per f-tile (2112)
#define EPOCH_F 4

// dynamic smem layout (words): tiles [2][EPOCH_F][FTILE], then meta [2][EPOCH_F*256] uint2
#define TILE_WORDS (2 * EPOCH_F * FTILE)
#define META_OFF_W TILE_WORDS
#define SMEM_BYTES (TILE_WORDS * 4 + 2 * EPOCH_F * 256 * 8)   // 83968

// ---------------- static device scratch ----------------
__device__ uint2 g_meta[FDIM * BATCH];                   // [f][b]: {t*132, half2(1-l0, l0)}
__device__ float g_part[(size_t)FS * BATCH * CPAD];      // [fs][b][c]
__device__ float g_rspart[FS * CPAD];                    // [fs][c]

// ---------------- Kernel 1: precomputed meta (transposed store) ----------------
__global__ void __launch_bounds__(1024) embed_k(const float* __restrict__ x,
                                                const float* __restrict__ mn,
                                                const float* __restrict__ mx) {
    __shared__ uint2 sm[32][33];
    const int tx = threadIdx.x & 31;
    const int ty = threadIdx.x >> 5;
    const int f0 = blockIdx.x * 32;
    const int b0 = blockIdx.y * 32;

    const float mnv = mn[0], mxv = mx[0];
    const float s = (x[(size_t)(b0 + ty) * FDIM + f0 + tx] - mnv) / (mxv - mnv) * 63.0f;

    uint2 m;
    if (s >= 0.0f && s <= 63.0f) {
        int t = (int)s;
        if (t > 62) t = 62;
        const float l0 = s - (float)t;                    // weight of vertex t+1
        const __half2 lam2 = __floats2half2_rn(1.0f - l0, l0);
        m.x = (uint32_t)t * (TSTRIDE * 4);
        m.y = *(const uint32_t*)&lam2;
    } else {
        m.x = 63u * (TSTRIDE * 4);                        // zero row sink
        m.y = 0u;                                         // zero lambda
    }
    sm[ty][tx] = m;
    __syncthreads();
    g_meta[(size_t)(f0 + ty) * BATCH + b0 + tx] = sm[tx][ty];
}

// ---------------- Kernel 2: 32-class CTAs, 2/SM co-resident ----------------
// CTA: 32 classes (cb) x f-slice x 256 b. tile[f4][t][c] = half2(W[c][t], W[c][t+1]).
// Gather: warp w (0..7) -> b in [32w,32w+32); lane -> class lane.
// Fill: thread (row=tid>>3, cg=tid&7) -> class row, cols 8cg..8cg+7.
__global__ void __launch_bounds__(THREADS, 2) gather_k(const float* __restrict__ W) {
    extern __shared__ uint32_t smw[];
    uint32_t* tiles = smw;
    uint2*    meta  = (uint2*)(smw + META_OFF_W);

    const int tid  = threadIdx.x;
    const int lane = tid & 31;
    const int w    = tid >> 5;       // 0..7
    const int cb   = blockIdx.x;     // 0..31
    const int fs   = blockIdx.y;     // 0..8
    // uneven epoch partition: slices 0..3 get 29 epochs, 4..8 get 28 (total 256)
    const int ebase = (fs < 4) ? 29 * fs : (29 * 4 + 28 * (fs - 4));
    const int ne    = (fs < 4) ? 29 : 28;
    const int fbase = ebase * EPOCH_F;

    // fill role
    const int frow = tid >> 3;       // class row 0..31
    const int cg   = tid & 7;        // column group (8 floats)
    int wrow = cb * 32 + frow;
    if (wrow > NCLS - 1) wrow = NCLS - 1;
    const float* wp = W + (size_t)wrow * KROW + (size_t)fbase * 64 + cg * 8;

    // meta role: thread covers 4 consecutive entries (f4m, bm..bm+3)
    const int f4m = tid >> 6;
    const int bm  = (tid & 63) * 4;
    const uint4* mp = (const uint4*)(g_meta + (size_t)(fbase + f4m) * BATCH + bm);

    uint32_t acch[32];
    float    accf[32];
    #pragma unroll
    for (int j = 0; j < 32; j++) { acch[j] = 0u; accf[j] = 0.f; }
    float rs = 0.f;

    // prologue prefetch: epoch 0
    float4 wv0[EPOCH_F], wv1[EPOCH_F];
    #pragma unroll
    for (int f4 = 0; f4 < EPOCH_F; f4++) {
        wv0[f4] = *(const float4*)(wp + f4 * 64);
        wv1[f4] = *(const float4*)(wp + f4 * 64 + 4);
    }
    uint4 mrA = mp[0], mrB = mp[1];

    for (int e = 0; e < ne; e++) {
        const int buf = e & 1;
        uint32_t* tbase = tiles + buf * (EPOCH_F * FTILE);

        // ---- fill pair sub-tiles + rowsum ----
        #pragma unroll
        for (int f4 = 0; f4 < EPOCH_F; f4++) {
            uint32_t* tb = tbase + f4 * FTILE;
            const float4 a = wv0[f4];
            const float4 b = wv1[f4];
            const float nx = __shfl_down_sync(0xffffffffu, a.x, 1);  // next cg's first col
            rs += (a.x + a.y) + (a.z + a.w) + (b.x + b.y) + (b.z + b.w);
            uint32_t pr[8]; __half2 h;
            h = __floats2half2_rn(a.x, a.y);  pr[0] = *(uint32_t*)&h;
            h = __floats2half2_rn(a.y, a.z);  pr[1] = *(uint32_t*)&h;
            h = __floats2half2_rn(a.z, a.w);  pr[2] = *(uint32_t*)&h;
            h = __floats2half2_rn(a.w, b.x);  pr[3] = *(uint32_t*)&h;
            h = __floats2half2_rn(b.x, b.y);  pr[4] = *(uint32_t*)&h;
            h = __floats2half2_rn(b.y, b.z);  pr[5] = *(uint32_t*)&h;
            h = __floats2half2_rn(b.z, b.w);  pr[6] = *(uint32_t*)&h;
            h = __floats2half2_rn(b.w, nx);   pr[7] = *(uint32_t*)&h;
            if (cg == 7) pr[7] = 0u;          // t=63 row: zero sink
            #pragma unroll
            for (int i = 0; i < 8; i++)
                tb[(8 * cg + i) * TSTRIDE + frow] = pr[i];
        }
        {
            uint2* md = meta + buf * (EPOCH_F * 256) + f4m * 256 + bm;
            *(uint4*)(md)     = mrA;
            *(uint4*)(md + 2) = mrB;
        }

        // ---- refill for epoch e+1 (LDG latency overlaps barrier + gather) ----
        if (e + 1 < ne) {
            const size_t off = (size_t)(EPOCH_F * (e + 1)) * 64;
            #pragma unroll
            for (int f4 = 0; f4 < EPOCH_F; f4++) {
                wv0[f4] = *(const float4*)(wp + off + f4 * 64);
                wv1[f4] = *(const float4*)(wp + off + f4 * 64 + 4);
            }
            const uint4* mpn = (const uint4*)((const uint2*)mp + (size_t)(EPOCH_F * (e + 1)) * BATCH);
            mrA = mpn[0]; mrB = mpn[1];
        }

        __syncthreads();

        // ---- gather 4 f's: per b: 1 conflict-free LDS.32 + 1 HFMA2 ----
        #pragma unroll
        for (int f4 = 0; f4 < EPOCH_F; f4++) {
            const char* tb = (const char*)(tbase + f4 * FTILE);
            const uint4* mb = (const uint4*)(meta + buf * (EPOCH_F * 256) + f4 * 256 + w * 32);
            #pragma unroll
            for (int q = 0; q < 16; q++) {
                const uint4 mq = mb[q];
                {
                    const int j = 2 * q;
                    const uint32_t p0 = *(const uint32_t*)(tb + mq.x + lane * 4);
                    const __half2 l2 = *(const __half2*)&mq.y;
                    __half2 a0 = *(__half2*)&acch[j];
                    a0 = __hfma2(l2, *(const __half2*)&p0, a0);
                    acch[j] = *(uint32_t*)&a0;
                }
                {
                    const int j = 2 * q + 1;
                    const uint32_t p0 = *(const uint32_t*)(tb + mq.z + lane * 4);
                    const __half2 l2 = *(const __half2*)&mq.w;
                    __half2 a0 = *(__half2*)&acch[j];
                    a0 = __hfma2(l2, *(const __half2*)&p0, a0);
                    acch[j] = *(uint32_t*)&a0;
                }
            }
        }

        // ---- drain f16 accumulators to fp32 every 4 epochs (16 f) ----
        if ((e & 3) == 3) {
            #pragma unroll
            for (int j = 0; j < 32; j++) {
                const float2 f2v = __half22float2(*(const __half2*)&acch[j]);
                accf[j] += f2v.x + f2v.y;
                acch[j] = 0u;
            }
        }
    }

    // ---- final drain (trailing epochs when ne % 4 != 0) ----
    #pragma unroll
    for (int j = 0; j < 32; j++) {
        const float2 f2v = __half22float2(*(const __half2*)&acch[j]);
        accf[j] += f2v.x + f2v.y;
    }

    // ---- rowsum: reduce over the 8 column groups (threads row*8+cg are consecutive) ----
    {
        float r = rs;
        r += __shfl_xor_sync(0xffffffffu, r, 1);
        r += __shfl_xor_sync(0xffffffffu, r, 2);
        r += __shfl_xor_sync(0xffffffffu, r, 4);
        if (cg == 0)
            g_rspart[fs * CPAD + cb * 32 + frow] = r;
    }

    // ---- store partials (coalesced 128B per b) ----
    #pragma unroll
    for (int j = 0; j < 32; j++) {
        float* pp = g_part + ((size_t)fs * BATCH + w * 32 + j) * CPAD + cb * 32;
        pp[lane] = accf[j];
    }
}

// ---------------- Kernel 3: reduce partials + rowsum term ----------------
__global__ void __launch_bounds__(256) epi_k(const float* __restrict__ mn,
                                             const float* __restrict__ mx,
                                             float* __restrict__ out) {
    const int b = blockIdx.x;
    const float mnv = mn[0], mxv = mx[0];
    const float sc = mxv - mnv;
    for (int c = threadIdx.x; c < NCLS; c += 256) {
        float s = 0.f, rsum = 0.f;
        #pragma unroll
        for (int fsl = 0; fsl < FS; fsl++) {
            s    += g_part[((size_t)fsl * BATCH + b) * CPAD + c];
            rsum += g_rspart[fsl * CPAD + c];
        }
        out[(size_t)b * NCLS + c] = sc * s + mnv * rsum;
    }
}

// ---------------- launch ----------------
extern "C" void kernel_launch(void* const* d_in, const int* in_sizes, int n_in,
                              void* d_out, int out_size) {
    const float* x  = (const float*)d_in[0];
    const float* mn = (const float*)d_in[1];
    const float* mx = (const float*)d_in[2];
    const float* W  = (const float*)d_in[3];
    float* out = (float*)d_out;

    embed_k<<<dim3(32, 8), 1024>>>(x, mn, mx);

    cudaFuncSetAttribute(gather_k, cudaFuncAttributeMaxDynamicSharedMemorySize, SMEM_BYTES);
    gather_k<<<dim3(CB, FS), THREADS, SMEM_BYTES>>>(W);

    epi_k<<<BATCH, 256>>>(mn, mx, out);
}